// round 11
// baseline (speedup 1.0000x reference)
#include <cuda_runtime.h>

typedef unsigned long long u64;

// ---- packed f32x2 helpers (Blackwell; ptxas won't auto-fuse) ----
static __device__ __forceinline__ u64 pack2(float v) {
    u64 r; asm("mov.b64 %0, {%1, %1};" : "=l"(r) : "f"(v)); return r;
}
static __device__ __forceinline__ u64 mul2(u64 a, u64 b) {
    u64 r; asm("mul.rn.f32x2 %0, %1, %2;" : "=l"(r) : "l"(a), "l"(b)); return r;
}
static __device__ __forceinline__ u64 fma2(u64 a, u64 b, u64 c) {
    u64 r; asm("fma.rn.f32x2 %0, %1, %2, %3;" : "=l"(r) : "l"(a), "l"(b), "l"(c)); return r;
}
struct P4 { u64 a, b; };

// One 128-bit non-coherent load per corner: minimum L1 wavefronts.
static __device__ __forceinline__ P4 ld4v(const float4* __restrict__ p) {
    P4 r;
    asm("ld.global.nc.v2.u64 {%0, %1}, [%2];" : "=l"(r.a), "=l"(r.b) : "l"(p));
    return r;
}
static __device__ __forceinline__ P4 lerp4p(P4 A, P4 B, u64 WA, u64 WB) {
    P4 r;
    r.a = fma2(A.a, WA, mul2(B.a, WB));
    r.b = fma2(A.b, WA, mul2(B.b, WB));
    return r;
}

// streaming stores: keep the 91MB output from evicting the ~78MB feature set in L2
static __device__ __forceinline__ void st128cs(float* p, u64 a, u64 b) {
    asm volatile("st.global.cs.v2.u64 [%0], {%1, %2};" :: "l"(p), "l"(a), "l"(b));
}
static __device__ __forceinline__ void st64cs(float* p, u64 a) {
    asm volatile("st.global.cs.u64 [%0], %1;" :: "l"(p), "l"(a));
}
static __device__ __forceinline__ void st32cs(float* p, float a) {
    asm volatile("st.global.cs.f32 [%0], %1;" :: "l"(p), "f"(a));
}

// Multi-res trilinear sampling. Levels 1 (64^3x32), 2 (32^3x64), 3 (16^3x128).
// Out per point: [32 | 64 | 128 | mesh 3] = 227 floats.
// Persistent grid-stride: each thread owns one slot (64 threads/point,
// 4 channels/thread) and loops over points; slot-derived constants hoist.
//   slot 0..7 -> lev1, 8..23 -> lev2, 24..55 -> lev3, 56..58 -> mesh.
__global__ void __launch_bounds__(256, 8) trilerp_kernel(
    const float* __restrict__ f1, const float* __restrict__ f2, const float* __restrict__ f3,
    const float* __restrict__ coords, const float* __restrict__ meshf,
    float* __restrict__ out, int Npts)
{
    int slot = threadIdx.x & 63;
    int grp0 = (blockIdx.x * 256 + threadIdx.x) >> 6;  // starting point index in batch
    int stride = gridDim.x * 4;                        // point groups per grid step
    int b = blockIdx.y;

    // ---- hoisted slot-derived constants (loop-invariant) ----
    int lev = (slot < 8) ? 1 : ((slot < 24) ? 2 : 3);
    const float4* __restrict__ fp =
        (const float4*)((lev == 1) ? f1 : ((lev == 2) ? f2 : f3));
    int cstart = (lev == 1) ? 0 : ((lev == 2) ? 8 : 24);
    int R   = 128 >> lev;          // 64 / 32 / 16
    int s4  = 4 << lev;            // C/4 = 8 / 16 / 32
    int Rs4 = R * s4;
    int RRs4 = R * Rs4;
    int bbase = b * R * RRs4 + (slot - cstart);  // batch offset + channel base
    float scale = (float)R;        // 0.5^lev * 128 == R
    float hi = scale - 1.01f;
    bool mesh = (slot >= 56);
    int mk = slot - 56;

    if (grp0 >= Npts) return;

    // prefetch first coords
    const float* cp = coords + ((size_t)b * Npts + grp0) * 3;
    float cx = __ldg(cp + 0), cy = __ldg(cp + 1), cz = __ldg(cp + 2);

    for (int pInB = grp0; pInB < Npts; pInB += stride) {
        int nxt = pInB + stride;
        float nx = 0.f, ny = 0.f, nz = 0.f;
        if (nxt < Npts) {  // prefetch next point's coords (overlaps this gather)
            const float* np = coords + ((size_t)b * Npts + nxt) * 3;
            nx = __ldg(np + 0); ny = __ldg(np + 1); nz = __ldg(np + 2);
        }

        int point = b * Npts + pInB;
        size_t obase = (size_t)point * 227;

        if (mesh) {
            if (mk < 3) st32cs(out + obase + 224 + mk, __ldg(meshf + point * 3 + mk));
        } else {
            float ix = fminf(fmaxf(cx * scale, 0.01f), hi);
            float iy = fminf(fmaxf(cy * scale, 0.01f), hi);
            float iz = fminf(fmaxf(cz * scale, 0.01f), hi);

            float fx1 = floorf(ix), fx2 = ceilf(ix);
            float fy1 = floorf(iy), fy2 = ceilf(iy);
            float fz1 = floorf(iz), fz2 = ceilf(iz);

            u64 WX = pack2(ix - fx1), WX2 = pack2(fx2 - ix);
            u64 WY = pack2(iy - fy1), WY2 = pack2(fy2 - iy);
            u64 WZ = pack2(iz - fz1), WZ2 = pack2(fz2 - iz);

            int x1 = (int)fx1, y1 = (int)fy1, z1 = (int)fz1;
            int dxs = ((int)fx2 - x1) * RRs4;
            int dys = ((int)fy2 - y1) * Rs4;
            int dzs = ((int)fz2 - z1) * s4;
            const float4* p = fp + (bbase + x1 * RRs4 + y1 * Rs4 + z1 * s4);

            P4 v111 = ld4v(p);
            P4 v211 = ld4v(p + dxs);
            P4 v121 = ld4v(p + dys);
            P4 v221 = ld4v(p + dxs + dys);
            P4 v112 = ld4v(p + dzs);
            P4 v212 = ld4v(p + dxs + dzs);
            P4 v122 = ld4v(p + dys + dzs);
            P4 v222 = ld4v(p + dxs + dys + dzs);

            P4 la = lerp4p(v211, v111, WX, WX2);
            P4 lb = lerp4p(v221, v121, WX, WX2);
            P4 l1 = lerp4p(lb, la, WY, WY2);
            P4 lc = lerp4p(v212, v112, WX, WX2);
            P4 ld_ = lerp4p(v222, v122, WX, WX2);
            P4 l2 = lerp4p(ld_, lc, WY, WY2);
            P4 r  = lerp4p(l2, l1, WZ, WZ2);

            unsigned omod = (unsigned)(obase & 3);   // warp-uniform per point
            float* q = out + obase + 4 * slot;
            if (omod == 0) {
                st128cs(q, r.a, r.b);
            } else if ((omod & 1) == 0) {
                st64cs(q, r.a);
                st64cs(q + 2, r.b);
            } else {
                float a0, a1, b0, b1;
                asm("mov.b64 {%0,%1}, %2;" : "=f"(a0), "=f"(a1) : "l"(r.a));
                asm("mov.b64 {%0,%1}, %2;" : "=f"(b0), "=f"(b1) : "l"(r.b));
                st32cs(q + 0, a0); st32cs(q + 1, a1);
                st32cs(q + 2, b0); st32cs(q + 3, b1);
            }
        }

        cx = nx; cy = ny; cz = nz;
    }
}

extern "C" void kernel_launch(void* const* d_in, const int* in_sizes, int n_in,
                              void* d_out, int out_size)
{
    // metadata order: features0..features4, mesh_coords, mesh_features
    const float* f1     = (const float*)d_in[1];
    const float* f2     = (const float*)d_in[2];
    const float* f3     = (const float*)d_in[3];
    const float* coords = (const float*)d_in[5];
    const float* meshf  = (const float*)d_in[6];
    float* out = (float*)d_out;

    int B    = in_sizes[1] / (64 * 64 * 64 * 32);
    int BN   = in_sizes[5] / 3;
    int Npts = BN / B;

    // persistent-ish: 148 SMs x 8 blocks = 1184 resident blocks; split over B in y
    int gx = 1184 / (B > 0 ? B : 1);
    if (gx < 1) gx = 1;
    // don't launch more groups than points
    long long maxgx = ((long long)Npts * 64 + 255) / 256;
    if (gx > maxgx) gx = (int)maxgx;
    dim3 grid((unsigned)gx, (unsigned)B);
    trilerp_kernel<<<grid, 256>>>(f1, f2, f3, coords, meshf, out, Npts);
}

// round 12
// speedup vs baseline: 1.5251x; 1.5251x over previous
#include <cuda_runtime.h>

typedef unsigned long long u64;

// ---- packed f32x2 helpers (Blackwell; ptxas won't auto-fuse) ----
static __device__ __forceinline__ u64 pack2(float v) {
    u64 r; asm("mov.b64 %0, {%1, %1};" : "=l"(r) : "f"(v)); return r;
}
static __device__ __forceinline__ u64 mul2(u64 a, u64 b) {
    u64 r; asm("mul.rn.f32x2 %0, %1, %2;" : "=l"(r) : "l"(a), "l"(b)); return r;
}
static __device__ __forceinline__ u64 fma2(u64 a, u64 b, u64 c) {
    u64 r; asm("fma.rn.f32x2 %0, %1, %2, %3;" : "=l"(r) : "l"(a), "l"(b), "l"(c)); return r;
}
struct P4 { u64 a, b; };

// One 128-bit non-coherent load per corner: minimum L1 wavefronts.
static __device__ __forceinline__ P4 ld4v(const float4* __restrict__ p) {
    P4 r;
    asm("ld.global.nc.v2.u64 {%0, %1}, [%2];" : "=l"(r.a), "=l"(r.b) : "l"(p));
    return r;
}
static __device__ __forceinline__ P4 lerp4p(P4 A, P4 B, u64 WA, u64 WB) {
    P4 r;
    r.a = fma2(A.a, WA, mul2(B.a, WB));
    r.b = fma2(A.b, WA, mul2(B.b, WB));
    return r;
}

// streaming stores: keep the 91MB output from evicting the ~78MB feature set in L2
static __device__ __forceinline__ void st128cs(float* p, u64 a, u64 b) {
    asm volatile("st.global.cs.v2.u64 [%0], {%1, %2};" :: "l"(p), "l"(a), "l"(b));
}
static __device__ __forceinline__ void st64cs(float* p, u64 a) {
    asm volatile("st.global.cs.u64 [%0], %1;" :: "l"(p), "l"(a));
}
static __device__ __forceinline__ void st32cs(float* p, float a) {
    asm volatile("st.global.cs.f32 [%0], %1;" :: "l"(p), "f"(a));
}

// Multi-res trilinear sampling. Levels 1 (64^3x32), 2 (32^3x64), 3 (16^3x128).
// Out per point: [32 | 64 | 128 | mesh 3] = 227 floats.
// Block = 224 threads = 4 points x 56 active slots (NO idle lanes):
//   slot 0..7 -> lev1, 8..23 -> lev2, 24..55 -> lev3.
//   mesh passthrough (3 floats) folded onto slot==0 lanes.
// Global out channel = 4*slot (concat offsets align).
// __launch_bounds__(224, 9): <=32 regs -> 9 blocks = 63 warps/SM resident.
__global__ void __launch_bounds__(224, 9) trilerp_kernel(
    const float* __restrict__ f1, const float* __restrict__ f2, const float* __restrict__ f3,
    const float* __restrict__ coords, const float* __restrict__ meshf,
    float* __restrict__ out, int Npts)
{
    int tid = threadIdx.x;
    int pt   = tid / 56;          // 0..3
    int slot = tid - pt * 56;     // 0..55
    int pInB = blockIdx.x * 4 + pt;
    if (pInB >= Npts) return;
    int b = blockIdx.y;
    int point = b * Npts + pInB;
    size_t obase = (size_t)point * 227;

    float cx = __ldg(coords + point * 3 + 0);
    float cy = __ldg(coords + point * 3 + 1);
    float cz = __ldg(coords + point * 3 + 2);

    int lev = (slot < 8) ? 1 : ((slot < 24) ? 2 : 3);
    const float4* __restrict__ fp =
        (const float4*)((lev == 1) ? f1 : ((lev == 2) ? f2 : f3));
    int cstart = (lev == 1) ? 0 : ((lev == 2) ? 8 : 24);
    int R  = 128 >> lev;         // 64 / 32 / 16
    int s4 = 4 << lev;           // C/4 = 8 / 16 / 32
    int c4 = slot - cstart;      // channel base in float4 units

    float scale = (float)R;      // 0.5^lev * 128 == R
    float hi = scale - 1.01f;
    float ix = fminf(fmaxf(cx * scale, 0.01f), hi);
    float iy = fminf(fmaxf(cy * scale, 0.01f), hi);
    float iz = fminf(fmaxf(cz * scale, 0.01f), hi);

    float fx1 = floorf(ix), fx2 = ceilf(ix);
    float fy1 = floorf(iy), fy2 = ceilf(iy);
    float fz1 = floorf(iz), fz2 = ceilf(iz);

    u64 WX = pack2(ix - fx1), WX2 = pack2(fx2 - ix);
    u64 WY = pack2(iy - fy1), WY2 = pack2(fy2 - iy);
    u64 WZ = pack2(iz - fz1), WZ2 = pack2(fz2 - iz);

    int x1 = (int)fx1, y1 = (int)fy1, z1 = (int)fz1;
    // corner step offsets (0 or one full stride) in float4 units
    int dxs = ((int)fx2 - x1) * R * R * s4;
    int dys = ((int)fy2 - y1) * R * s4;
    int dzs = ((int)fz2 - z1) * s4;
    const float4* p = fp + (((b * R + x1) * R + y1) * R + z1) * s4 + c4;

    // 8 independent LDG.128s (front-batched; wavefronts = lines = floor)
    P4 v111 = ld4v(p);
    P4 v211 = ld4v(p + dxs);
    P4 v121 = ld4v(p + dys);
    P4 v221 = ld4v(p + dxs + dys);
    P4 v112 = ld4v(p + dzs);
    P4 v212 = ld4v(p + dxs + dzs);
    P4 v122 = ld4v(p + dys + dzs);
    P4 v222 = ld4v(p + dxs + dys + dzs);

    // mesh passthrough on slot-0 lanes (overlaps gather latency)
    if (slot == 0) {
        st32cs(out + obase + 224, __ldg(meshf + point * 3 + 0));
        st32cs(out + obase + 225, __ldg(meshf + point * 3 + 1));
        st32cs(out + obase + 226, __ldg(meshf + point * 3 + 2));
    }

    // z = z1 plane
    P4 la = lerp4p(v211, v111, WX, WX2);
    P4 lb = lerp4p(v221, v121, WX, WX2);
    P4 l1 = lerp4p(lb, la, WY, WY2);
    // z = z2 plane
    P4 lc = lerp4p(v212, v112, WX, WX2);
    P4 ld_ = lerp4p(v222, v122, WX, WX2);
    P4 l2 = lerp4p(ld_, lc, WY, WY2);

    P4 r = lerp4p(l2, l1, WZ, WZ2);

    // alignment class per point (may diverge within a warp spanning 2 points)
    unsigned omod = (unsigned)(obase & 3);
    float* q = out + obase + 4 * slot;
    if (omod == 0) {
        st128cs(q, r.a, r.b);                 // STG.128
    } else if ((omod & 1) == 0) {
        st64cs(q, r.a);                       // 2x STG.64
        st64cs(q + 2, r.b);
    } else {
        float a0, a1, b0, b1;
        asm("mov.b64 {%0,%1}, %2;" : "=f"(a0), "=f"(a1) : "l"(r.a));
        asm("mov.b64 {%0,%1}, %2;" : "=f"(b0), "=f"(b1) : "l"(r.b));
        st32cs(q + 0, a0); st32cs(q + 1, a1);
        st32cs(q + 2, b0); st32cs(q + 3, b1);
    }
}

extern "C" void kernel_launch(void* const* d_in, const int* in_sizes, int n_in,
                              void* d_out, int out_size)
{
    // metadata order: features0..features4, mesh_coords, mesh_features
    const float* f1     = (const float*)d_in[1];
    const float* f2     = (const float*)d_in[2];
    const float* f3     = (const float*)d_in[3];
    const float* coords = (const float*)d_in[5];
    const float* meshf  = (const float*)d_in[6];
    float* out = (float*)d_out;

    int B    = in_sizes[1] / (64 * 64 * 64 * 32);
    int BN   = in_sizes[5] / 3;
    int Npts = BN / B;

    dim3 grid((unsigned)((Npts + 3) / 4), (unsigned)B);
    trilerp_kernel<<<grid, 224>>>(f1, f2, f3, coords, meshf, out, Npts);
}